// round 12
// baseline (speedup 1.0000x reference)
#include <cuda_runtime.h>
#include <cuda_bf16.h>

#define NBINS 100
#define THREADS 256
#define BLOCKS 1184          // 8 blocks/SM on 148 SMs, single wave

__device__ int g_hist[NBINS];
__device__ unsigned int g_ticket;   // zero-init; restored to 0 every launch

__global__ void __launch_bounds__(THREADS, 8) hist_kernel(
    const float4* __restrict__ x4, int n4,
    const float* __restrict__ tail, int ntail,
    const float* __restrict__ bounds,
    float* __restrict__ out)
{
    __shared__ __align__(16) float sb[NBINS + 1];
    __shared__ __align__(16) int   sh[NBINS * 32];  // sh[bin*32+lane], bank==lane
    __shared__ int is_last;

    const int tid  = threadIdx.x;
    const int lane = tid & 31;

    if (tid <= NBINS) sb[tid] = bounds[tid];
    for (int i = tid; i < NBINS * 32; i += THREADS) sh[i] = 0;
    __syncthreads();

    // e = (x + 1e-6) * 100/1.000001 ; int part = bin. Exact except within
    // ~2.2e-5 (e-units) of an integer boundary; m = 2.5e-4 is a 10x margin.
    // Danger test: |e - rint(e)| < m  (== old f<m || f>1-m, one predicate).
    const float scale = 100.0f / 1.000001f;
    const float coff  = 1e-6f * (100.0f / 1.000001f);
    const float m     = 2.5e-4f;

    const int stride = gridDim.x * THREADS;
    int i = blockIdx.x * THREADS + tid;

    for (; i + stride < n4; i += 2 * stride) {
        float4 v0 = __ldcs(&x4[i]);
        float4 v1 = __ldcs(&x4[i + stride]);

        float xs[8] = {v0.x, v0.y, v0.z, v0.w, v1.x, v1.y, v1.z, v1.w};
        #pragma unroll
        for (int k = 0; k < 8; k++) {
            const float x = xs[k];
            const float e = fmaf(x, scale, coff);            // FFMA
            const float d = e - rintf(e);                    // FRND + FADD
            int b = min((int)e, NBINS - 1);                  // F2I + IMNMX
            if (fabsf(d) < m) {                  // rare exact path (~0.05%)
                if (x <= sb[b])          b -= 1; // no-op if already correct
                else if (x > sb[b + 1])  b += 1;
                b = max(0, min(b, NBINS - 1));
            }
            atomicAdd(&sh[(b << 5) | lane], 1);              // bank = lane
        }
    }

    if (i < n4) {                                // one leftover float4 chunk
        float4 v0 = __ldcs(&x4[i]);
        float xs[4] = {v0.x, v0.y, v0.z, v0.w};
        #pragma unroll
        for (int k = 0; k < 4; k++) {
            const float x = xs[k];
            const float e = fmaf(x, scale, coff);
            const float d = e - rintf(e);
            int b = min((int)e, NBINS - 1);
            if (fabsf(d) < m) {
                if (x <= sb[b])          b -= 1;
                else if (x > sb[b + 1])  b += 1;
                b = max(0, min(b, NBINS - 1));
            }
            atomicAdd(&sh[(b << 5) | lane], 1);
        }
    }

    if (blockIdx.x == 0 && tid < ntail) {        // scalar tail
        const float x = tail[tid];
        const float e = fmaf(x, scale, coff);
        const float d = e - rintf(e);
        int b = min((int)e, NBINS - 1);
        if (fabsf(d) < m) {
            if (x <= sb[b])          b -= 1;
            else if (x > sb[b + 1])  b += 1;
            b = max(0, min(b, NBINS - 1));
        }
        atomicAdd(&sh[(b << 5) | lane], 1);
    }

    __syncthreads();

    // reduce: thread b sums its bin's 32 lane-counters as 8 int4 reads
    // (sh is 16B-aligned; bin*128B + j*16B keeps threads on distinct banks)
    if (tid < NBINS) {
        const int4* __restrict__ p = (const int4*)&sh[tid << 5];
        int s = 0;
        #pragma unroll
        for (int j = 0; j < 8; j++) {
            int4 v = p[j];
            s += v.x + v.y + v.z + v.w;
        }
        if (s) atomicAdd(&g_hist[tid], s);
    }

    // last block writes the result and restores globals for the next replay
    __threadfence();
    if (tid == 0) {
        unsigned int old = atomicAdd(&g_ticket, 1u);
        is_last = (old == (unsigned int)(gridDim.x - 1));
    }
    __syncthreads();

    if (is_last) {
        if (tid < NBINS) {
            int v = atomicAdd(&g_hist[tid], 0);  // L2-coherent read
            out[tid] = (float)v;
            atomicExch(&g_hist[tid], 0);
        }
        if (tid == 0) atomicExch(&g_ticket, 0u);
    }
}

extern "C" void kernel_launch(void* const* d_in, const int* in_sizes, int n_in,
                              void* d_out, int out_size) {
    const float* x      = (const float*)d_in[0];
    const float* bounds = (const float*)d_in[1];
    const int n  = in_sizes[0];
    const int n4 = n >> 2;
    const int ntail = n & 3;

    hist_kernel<<<BLOCKS, THREADS>>>((const float4*)x, n4,
                                     x + (n4 << 2), ntail, bounds,
                                     (float*)d_out);
}